// round 1
// baseline (speedup 1.0000x reference)
#include <cuda_runtime.h>
#include <math.h>

#define BB 16
#define LL 2048
#define HH 256
#define NS 64
#define NLAYER 4
#define FIN 75
#define G2 512
#define REPR 512

// ---- device scratch (allocation-free: static device globals) ----
__device__ float g_hT[BB*LL*HH];     // residual stream, token-major (B,L,H)
__device__ float g_ucm[BB*HH*LL];    // LN output, channel-major (B,H,L)
__device__ float g_ycm[BB*HH*LL];    // scan output (post skip+gelu), channel-major
__device__ float g_wr[NLAYER*HH*NS];
__device__ float g_wi[NLAYER*HH*NS];
__device__ float g_cr[NLAYER*HH*NS]; // 2*C_disc (factor 2 folded in)
__device__ float g_ci[NLAYER*HH*NS];

// ---------------------------------------------------------------------------
// Precompute discretized SSM parameters: w = exp(dt*A), Cd = 2*C*(w-1)/A
// ---------------------------------------------------------------------------
__global__ void precompute_kernel(const float* __restrict__ log_dt,
                                  const float* __restrict__ A_log_re,
                                  const float* __restrict__ A_im,
                                  const float* __restrict__ C_re,
                                  const float* __restrict__ C_im) {
    int idx = blockIdx.x * blockDim.x + threadIdx.x;
    if (idx >= NLAYER*HH*NS) return;
    int i = idx / (HH*NS);
    int h = (idx / NS) % HH;
    float dt  = expf(log_dt[i*HH + h]);
    float Are = -expf(A_log_re[idx]);
    float Aim = A_im[idx];
    float er = dt*Are, ei = dt*Aim;
    float mag = expf(er);
    float wr = mag*cosf(ei), wi = mag*sinf(ei);
    // (w-1)/A = (w-1)*conj(A)/|A|^2
    float nr = wr - 1.0f, ni = wi;
    float den = Are*Are + Aim*Aim;
    float inv = 1.0f/den;
    float qr = (nr*Are + ni*Aim)*inv;
    float qi = (ni*Are - nr*Aim)*inv;
    float cr = C_re[idx], ci = C_im[idx];
    g_wr[idx] = wr; g_wi[idx] = wi;
    g_cr[idx] = 2.0f*(cr*qr - ci*qi);
    g_ci[idx] = 2.0f*(cr*qi + ci*qr);
}

// ---------------------------------------------------------------------------
// Embed: (B*L,75) @ (75,256) + b -> g_hT token-major
// ---------------------------------------------------------------------------
__global__ void embed_kernel(const float* __restrict__ x,
                             const float* __restrict__ W,
                             const float* __restrict__ bias) {
    __shared__ float xs[FIN];
    int row = blockIdx.x;         // b*L + l
    int t = threadIdx.x;          // output channel
    if (t < FIN) xs[t] = x[(size_t)row*FIN + t];
    __syncthreads();
    float acc = bias[t];
    #pragma unroll 5
    for (int f = 0; f < FIN; f++) acc = fmaf(xs[f], W[f*HH + t], acc);
    g_hT[(size_t)row*HH + t] = acc;
}

// ---------------------------------------------------------------------------
// LayerNorm over H (token-major input) + transpose to channel-major
// Block: 256 threads, 32 tokens.
// ---------------------------------------------------------------------------
__global__ void ln_kernel(const float* __restrict__ gvec,
                          const float* __restrict__ bvec) {
    __shared__ float s[32][HH+1];
    __shared__ float sg[HH], sb[HH];
    int tid = threadIdx.x;
    sg[tid] = gvec[tid]; sb[tid] = bvec[tid];
    int blk = blockIdx.x;                 // 0 .. B*L/32-1
    int b = blk / (LL/32);
    int l0 = (blk % (LL/32)) * 32;
    int warp = tid >> 5, lane = tid & 31;
    __syncthreads();
    for (int tt = 0; tt < 4; tt++) {
        int t = warp*4 + tt;
        const float* p = g_hT + ((size_t)(b*LL + l0 + t))*HH;
        float v[8];
        float sum = 0.f;
        #pragma unroll
        for (int j = 0; j < 8; j++) { v[j] = p[lane + 32*j]; sum += v[j]; }
        #pragma unroll
        for (int o = 16; o; o >>= 1) sum += __shfl_xor_sync(0xffffffffu, sum, o);
        float mean = sum * (1.0f/HH);
        float var = 0.f;
        #pragma unroll
        for (int j = 0; j < 8; j++) { float d = v[j]-mean; var = fmaf(d, d, var); }
        #pragma unroll
        for (int o = 16; o; o >>= 1) var += __shfl_xor_sync(0xffffffffu, var, o);
        float rstd = rsqrtf(var*(1.0f/HH) + 1e-5f);
        #pragma unroll
        for (int j = 0; j < 8; j++) {
            int c = lane + 32*j;
            s[t][c] = (v[j]-mean)*rstd*sg[c] + sb[c];
        }
    }
    __syncthreads();
    // transpose out: channel-major writes, coalesced over l
    #pragma unroll 4
    for (int it = 0; it < 32; it++) {
        int h = it*8 + (tid >> 5);
        int ll = tid & 31;
        g_ucm[((size_t)(b*HH + h))*LL + l0 + ll] = s[ll][h];
    }
}

// ---------------------------------------------------------------------------
// Diagonal-SSM scan: warp per (b,h), 2 complex states per lane.
// y = gelu(conv(u) + D*u), written channel-major.
// ---------------------------------------------------------------------------
__global__ void scan_kernel(int layer, const float* __restrict__ Dski) {
    int wg = blockIdx.x*8 + (threadIdx.x >> 5);   // 0..B*H-1
    int lane = threadIdx.x & 31;
    int h = wg % HH;
    int base = layer*HH*NS + h*NS;
    float w0r = g_wr[base+lane],    w0i = g_wi[base+lane];
    float w1r = g_wr[base+32+lane], w1i = g_wi[base+32+lane];
    float c0r = g_cr[base+lane],    c0i = g_ci[base+lane];
    float c1r = g_cr[base+32+lane], c1i = g_ci[base+32+lane];
    float D = Dski[h];
    float s0r=0.f, s0i=0.f, s1r=0.f, s1i=0.f;
    const float* u = g_ucm + (size_t)wg*LL;
    float* y = g_ycm + (size_t)wg*LL;
    for (int l0 = 0; l0 < LL; l0 += 32) {
        float uj = u[l0 + lane];
        float my = 0.f;
        #pragma unroll
        for (int k = 0; k < 32; k++) {
            float uk = __shfl_sync(0xffffffffu, uj, k);
            float t0r = fmaf(w0r, s0r, fmaf(-w0i, s0i, uk));
            float t0i = fmaf(w0r, s0i, w0i*s0r);
            s0r = t0r; s0i = t0i;
            float t1r = fmaf(w1r, s1r, fmaf(-w1i, s1i, uk));
            float t1i = fmaf(w1r, s1i, w1i*s1r);
            s1r = t1r; s1i = t1i;
            float c = fmaf(c0r, s0r, -c0i*s0i);
            c = fmaf(c1r, s1r, c);
            c = fmaf(-c1i, s1i, c);
            #pragma unroll
            for (int o = 16; o; o >>= 1) c += __shfl_xor_sync(0xffffffffu, c, o);
            float yv = fmaf(D, uk, c);
            if (k == lane) my = yv;
        }
        // gelu (tanh approximation, matching jax.nn.gelu default)
        float x3 = my*my*my;
        float gl = 0.5f*my*(1.0f + tanhf(0.7978845608028654f*fmaf(0.044715f, x3, my)));
        y[l0 + lane] = gl;
    }
}

// ---------------------------------------------------------------------------
// GLU out-projection + residual:
//   z1 = Y@W1^T + b1, z2 = Y@W2^T + b2, h += z1*sigmoid(z2)
// A read channel-major (transpose fused into load). Tile 64(l) x 64(g) x 16(k),
// each block also computes the paired z2 columns (g+256).
// ---------------------------------------------------------------------------
__global__ void glu_kernel(const float* __restrict__ W,
                           const float* __restrict__ bias) {
    __shared__ float As[16*64];
    __shared__ float Bs1[16*68];
    __shared__ float Bs2[16*68];
    int tid = threadIdx.x;
    int g0 = blockIdx.x * 64;          // z1 column tile
    int mt = blockIdx.y;
    int b  = mt >> 5;                  // L/64 = 32 m-tiles per batch
    int l0 = (mt & 31) * 64;
    int tx = tid & 15, ty = tid >> 4;
    float acc1[4][4] = {{0}}, acc2[4][4] = {{0}};
    for (int k0 = 0; k0 < HH; k0 += 16) {
        #pragma unroll
        for (int t = 0; t < 4; t++) {
            int idx = tid + t*256;
            int kk = idx >> 6, ll = idx & 63;
            As[kk*64 + ll] = g_ycm[((size_t)(b*HH + k0 + kk))*LL + l0 + ll];
        }
        #pragma unroll
        for (int t = 0; t < 4; t++) {
            int idx = tid + t*256;
            int gg = idx >> 4, kk = idx & 15;
            Bs1[kk*68 + gg] = W[(g0 + gg)*HH + k0 + kk];
            Bs2[kk*68 + gg] = W[(g0 + 256 + gg)*HH + k0 + kk];
        }
        __syncthreads();
        #pragma unroll
        for (int kk = 0; kk < 16; kk++) {
            float4 a  = *(const float4*)&As [kk*64 + ty*4];
            float4 b1 = *(const float4*)&Bs1[kk*68 + tx*4];
            float4 b2 = *(const float4*)&Bs2[kk*68 + tx*4];
            float av[4]  = {a.x, a.y, a.z, a.w};
            float b1v[4] = {b1.x, b1.y, b1.z, b1.w};
            float b2v[4] = {b2.x, b2.y, b2.z, b2.w};
            #pragma unroll
            for (int r = 0; r < 4; r++)
                #pragma unroll
                for (int c = 0; c < 4; c++) {
                    acc1[r][c] = fmaf(av[r], b1v[c], acc1[r][c]);
                    acc2[r][c] = fmaf(av[r], b2v[c], acc2[r][c]);
                }
        }
        __syncthreads();
    }
    #pragma unroll
    for (int r = 0; r < 4; r++) {
        size_t orow = ((size_t)(b*LL + l0 + ty*4 + r))*HH + g0 + tx*4;
        #pragma unroll
        for (int c = 0; c < 4; c++) {
            float z1 = acc1[r][c] + bias[g0 + tx*4 + c];
            float z2 = acc2[r][c] + bias[256 + g0 + tx*4 + c];
            float sig = 1.0f/(1.0f + expf(-z2));
            g_hT[orow + c] += z1*sig;      // residual add in place
        }
    }
}

// ---------------------------------------------------------------------------
// Decoder: (B*L,256) @ (256,512) + b -> out
// ---------------------------------------------------------------------------
__global__ void dec_kernel(const float* __restrict__ W,
                           const float* __restrict__ bias,
                           float* __restrict__ out) {
    __shared__ float As[16*68];    // [k][l], transposed on load
    __shared__ float Bs[16*64];
    int tid = threadIdx.x;
    int r0 = blockIdx.x * 64;
    int m0 = blockIdx.y * 64;      // global token base
    int tx = tid & 15, ty = tid >> 4;
    float acc[4][4] = {{0}};
    for (int k0 = 0; k0 < HH; k0 += 16) {
        #pragma unroll
        for (int t = 0; t < 4; t++) {
            int idx = tid + t*256;
            int row = idx >> 4, col = idx & 15;
            As[col*68 + row] = g_hT[((size_t)(m0 + row))*HH + k0 + col];
        }
        #pragma unroll
        for (int t = 0; t < 4; t++) {
            int idx = tid + t*256;
            int kk = idx >> 6, rr = idx & 63;
            Bs[kk*64 + rr] = W[(k0 + kk)*REPR + r0 + rr];
        }
        __syncthreads();
        #pragma unroll
        for (int kk = 0; kk < 16; kk++) {
            float4 a = *(const float4*)&As[kk*68 + ty*4];
            float4 bb = *(const float4*)&Bs[kk*64 + tx*4];
            float av[4] = {a.x, a.y, a.z, a.w};
            float bv[4] = {bb.x, bb.y, bb.z, bb.w};
            #pragma unroll
            for (int r = 0; r < 4; r++)
                #pragma unroll
                for (int c = 0; c < 4; c++)
                    acc[r][c] = fmaf(av[r], bv[c], acc[r][c]);
        }
        __syncthreads();
    }
    #pragma unroll
    for (int r = 0; r < 4; r++) {
        size_t orow = ((size_t)(m0 + ty*4 + r))*REPR + r0 + tx*4;
        #pragma unroll
        for (int c = 0; c < 4; c++)
            out[orow + c] = acc[r][c] + bias[r0 + tx*4 + c];
    }
}

// ---------------------------------------------------------------------------
extern "C" void kernel_launch(void* const* d_in, const int* in_sizes, int n_in,
                              void* d_out, int out_size) {
    const float* x        = (const float*)d_in[0];
    const float* embed_W  = (const float*)d_in[1];
    const float* embed_b  = (const float*)d_in[2];
    const float* log_dt   = (const float*)d_in[3];
    const float* A_log_re = (const float*)d_in[4];
    const float* A_im     = (const float*)d_in[5];
    const float* C_re     = (const float*)d_in[6];
    const float* C_im     = (const float*)d_in[7];
    const float* D_skip   = (const float*)d_in[8];
    const float* out_W    = (const float*)d_in[9];
    const float* out_b    = (const float*)d_in[10];
    const float* ln_g     = (const float*)d_in[11];
    const float* ln_b     = (const float*)d_in[12];
    const float* dec_W    = (const float*)d_in[13];
    const float* dec_b    = (const float*)d_in[14];
    float* out = (float*)d_out;

    precompute_kernel<<<(NLAYER*HH*NS + 255)/256, 256>>>(log_dt, A_log_re, A_im, C_re, C_im);
    embed_kernel<<<BB*LL, 256>>>(x, embed_W, embed_b);
    for (int i = 0; i < NLAYER; i++) {
        ln_kernel<<<BB*LL/32, 256>>>(ln_g + i*HH, ln_b + i*HH);
        scan_kernel<<<BB*HH/8, 256>>>(i, D_skip + i*HH);
        glu_kernel<<<dim3(4, BB*LL/64), 256>>>(out_W + (size_t)i*G2*HH, out_b + i*G2);
    }
    dec_kernel<<<dim3(REPR/64, BB*LL/64), 256>>>(dec_W, dec_b, out);
}

// round 2
// speedup vs baseline: 1.1506x; 1.1506x over previous
#include <cuda_runtime.h>
#include <math.h>

#define BB 16
#define LL 2048
#define HH 256
#define NS 64
#define NLAYER 4
#define FIN 75
#define G2 512
#define REPR 512

// ---- device scratch (allocation-free: static device globals) ----
__device__ float g_hT[BB*LL*HH];     // residual stream, token-major (B,L,H)
__device__ float g_ucm[BB*HH*LL];    // LN output, channel-major (B,H,L)
__device__ float g_ycm[BB*HH*LL];    // scan output (post skip+gelu), channel-major
__device__ float g_wr[NLAYER*HH*NS];
__device__ float g_wi[NLAYER*HH*NS];
__device__ float g_cr[NLAYER*HH*NS]; // 2*C_disc (factor 2 folded in)
__device__ float g_ci[NLAYER*HH*NS];

// ---------------------------------------------------------------------------
// Precompute discretized SSM parameters: w = exp(dt*A), Cd = 2*C*(w-1)/A
// ---------------------------------------------------------------------------
__global__ void precompute_kernel(const float* __restrict__ log_dt,
                                  const float* __restrict__ A_log_re,
                                  const float* __restrict__ A_im,
                                  const float* __restrict__ C_re,
                                  const float* __restrict__ C_im) {
    int idx = blockIdx.x * blockDim.x + threadIdx.x;
    if (idx >= NLAYER*HH*NS) return;
    int i = idx / (HH*NS);
    int h = (idx / NS) % HH;
    float dt  = expf(log_dt[i*HH + h]);
    float Are = -expf(A_log_re[idx]);
    float Aim = A_im[idx];
    float er = dt*Are, ei = dt*Aim;
    float mag = expf(er);
    float wr = mag*cosf(ei), wi = mag*sinf(ei);
    // (w-1)/A = (w-1)*conj(A)/|A|^2
    float nr = wr - 1.0f, ni = wi;
    float den = Are*Are + Aim*Aim;
    float inv = 1.0f/den;
    float qr = (nr*Are + ni*Aim)*inv;
    float qi = (ni*Are - nr*Aim)*inv;
    float cr = C_re[idx], ci = C_im[idx];
    g_wr[idx] = wr; g_wi[idx] = wi;
    g_cr[idx] = 2.0f*(cr*qr - ci*qi);
    g_ci[idx] = 2.0f*(cr*qi + ci*qr);
}

// ---------------------------------------------------------------------------
// Embed: (B*L,75) @ (75,256) + b -> g_hT token-major.
// 32 tokens per block; W staged in dynamic smem once per block (76.8KB).
// ---------------------------------------------------------------------------
__global__ void embed_kernel(const float* __restrict__ x,
                             const float* __restrict__ W,
                             const float* __restrict__ bias) {
    extern __shared__ float Ws[];            // [75][256]
    __shared__ float xs[32*FIN];
    int t = threadIdx.x;                     // output column 0..255
    for (int i = t; i < FIN*HH; i += 256) Ws[i] = W[i];
    int row0 = blockIdx.x * 32;
    for (int i = t; i < 32*FIN; i += 256) xs[i] = x[(size_t)row0*FIN + i];
    __syncthreads();
    float acc[32];
    float b = bias[t];
    #pragma unroll
    for (int r = 0; r < 32; r++) acc[r] = b;
    for (int f = 0; f < FIN; f++) {
        float wf = Ws[f*HH + t];
        #pragma unroll
        for (int r = 0; r < 32; r++) acc[r] = fmaf(xs[r*FIN + f], wf, acc[r]);
    }
    #pragma unroll
    for (int r = 0; r < 32; r++)
        g_hT[((size_t)(row0 + r))*HH + t] = acc[r];
}

// ---------------------------------------------------------------------------
// LayerNorm over H (token-major input) + transpose to channel-major
// ---------------------------------------------------------------------------
__global__ void ln_kernel(const float* __restrict__ gvec,
                          const float* __restrict__ bvec) {
    __shared__ float s[32][HH+1];
    __shared__ float sg[HH], sb[HH];
    int tid = threadIdx.x;
    sg[tid] = gvec[tid]; sb[tid] = bvec[tid];
    int blk = blockIdx.x;                 // 0 .. B*L/32-1
    int b = blk / (LL/32);
    int l0 = (blk % (LL/32)) * 32;
    int warp = tid >> 5, lane = tid & 31;
    __syncthreads();
    for (int tt = 0; tt < 4; tt++) {
        int t = warp*4 + tt;
        const float* p = g_hT + ((size_t)(b*LL + l0 + t))*HH;
        float v[8];
        float sum = 0.f;
        #pragma unroll
        for (int j = 0; j < 8; j++) { v[j] = p[lane + 32*j]; sum += v[j]; }
        #pragma unroll
        for (int o = 16; o; o >>= 1) sum += __shfl_xor_sync(0xffffffffu, sum, o);
        float mean = sum * (1.0f/HH);
        float var = 0.f;
        #pragma unroll
        for (int j = 0; j < 8; j++) { float d = v[j]-mean; var = fmaf(d, d, var); }
        #pragma unroll
        for (int o = 16; o; o >>= 1) var += __shfl_xor_sync(0xffffffffu, var, o);
        float rstd = rsqrtf(var*(1.0f/HH) + 1e-5f);
        #pragma unroll
        for (int j = 0; j < 8; j++) {
            int c = lane + 32*j;
            s[t][c] = (v[j]-mean)*rstd*sg[c] + sb[c];
        }
    }
    __syncthreads();
    #pragma unroll 4
    for (int it = 0; it < 32; it++) {
        int h = it*8 + (tid >> 5);
        int ll = tid & 31;
        g_ucm[((size_t)(b*HH + h))*LL + l0 + ll] = s[ll][h];
    }
}

__device__ __forceinline__ float gelu_f(float v) {
    float x3 = v*v*v;
    return 0.5f*v*(1.0f + tanhf(fmaf(0.0356774081f, x3, 0.7978845608f*v)));
}

// ---------------------------------------------------------------------------
// Diagonal-SSM scan: 8 lanes per channel, 8 complex states per lane,
// 4 channels per warp. y = gelu(conv(u) + D*u), channel-major.
// ---------------------------------------------------------------------------
__global__ void __launch_bounds__(64) scan_kernel(int layer, const float* __restrict__ Dski) {
    int warpId = blockIdx.x*2 + (threadIdx.x >> 5);   // 0..1023
    int lane = threadIdx.x & 31;
    int s = lane & 7;                                  // sub-lane within channel group
    int ch = warpId*4 + (lane >> 3);                   // 0..B*H-1 (row index into g_ucm)
    int h = ch & (HH-1);
    int base = layer*HH*NS + h*NS + s*8;
    float wr[8], wi[8], cr[8], ci[8];
    #pragma unroll
    for (int k = 0; k < 8; k++) {
        wr[k] = g_wr[base+k]; wi[k] = g_wi[base+k];
        cr[k] = g_cr[base+k]; ci[k] = g_ci[base+k];
    }
    float sr[8], si[8];
    #pragma unroll
    for (int k = 0; k < 8; k++) { sr[k] = 0.f; si[k] = 0.f; }
    float D = Dski[h];
    const float* u = g_ucm + (size_t)ch*LL;
    float* y = g_ycm + (size_t)ch*LL;
    int srcbase = lane & ~7;

    for (int l0 = 0; l0 < LL; l0 += 32) {
        float u0 = u[l0 + s];
        float u1 = u[l0 + 8 + s];
        float u2 = u[l0 + 16 + s];
        float u3 = u[l0 + 24 + s];
        float my0 = 0.f, my1 = 0.f, my2 = 0.f, my3 = 0.f;
        #pragma unroll
        for (int t = 0; t < 32; t++) {
            float ut = (t < 8) ? u0 : (t < 16) ? u1 : (t < 24) ? u2 : u3;
            float uk = __shfl_sync(0xffffffffu, ut, srcbase + (t & 7));
            // update all 8 complex states
            #pragma unroll
            for (int k = 0; k < 8; k++) {
                float tr = fmaf(wr[k], sr[k], fmaf(-wi[k], si[k], uk));
                float ti = fmaf(wr[k], si[k], wi[k]*sr[k]);
                sr[k] = tr; si[k] = ti;
            }
            // projection: c = sum_k cr*sr - ci*si (4 accumulators for ILP)
            float a0 = fmaf(cr[0], sr[0], -ci[0]*si[0]);
            float a1 = fmaf(cr[1], sr[1], -ci[1]*si[1]);
            float a2 = fmaf(cr[2], sr[2], -ci[2]*si[2]);
            float a3 = fmaf(cr[3], sr[3], -ci[3]*si[3]);
            a0 = fmaf(cr[4], sr[4], a0); a0 = fmaf(-ci[4], si[4], a0);
            a1 = fmaf(cr[5], sr[5], a1); a1 = fmaf(-ci[5], si[5], a1);
            a2 = fmaf(cr[6], sr[6], a2); a2 = fmaf(-ci[6], si[6], a2);
            a3 = fmaf(cr[7], sr[7], a3); a3 = fmaf(-ci[7], si[7], a3);
            float c = (a0 + a1) + (a2 + a3);
            // reduce across the 8-lane group
            c += __shfl_xor_sync(0xffffffffu, c, 1);
            c += __shfl_xor_sync(0xffffffffu, c, 2);
            c += __shfl_xor_sync(0xffffffffu, c, 4);
            float yv = fmaf(D, uk, c);
            if ((t & 7) == s) {
                if (t < 8) my0 = yv; else if (t < 16) my1 = yv;
                else if (t < 24) my2 = yv; else my3 = yv;
            }
        }
        y[l0 + s]      = gelu_f(my0);
        y[l0 + 8 + s]  = gelu_f(my1);
        y[l0 + 16 + s] = gelu_f(my2);
        y[l0 + 24 + s] = gelu_f(my3);
    }
}

// ---------------------------------------------------------------------------
// GLU out-projection + residual
// ---------------------------------------------------------------------------
__global__ void glu_kernel(const float* __restrict__ W,
                           const float* __restrict__ bias) {
    __shared__ float As[16*64];
    __shared__ float Bs1[16*68];
    __shared__ float Bs2[16*68];
    int tid = threadIdx.x;
    int g0 = blockIdx.x * 64;
    int mt = blockIdx.y;
    int b  = mt >> 5;
    int l0 = (mt & 31) * 64;
    int tx = tid & 15, ty = tid >> 4;
    float acc1[4][4] = {{0}}, acc2[4][4] = {{0}};
    for (int k0 = 0; k0 < HH; k0 += 16) {
        #pragma unroll
        for (int t = 0; t < 4; t++) {
            int idx = tid + t*256;
            int kk = idx >> 6, ll = idx & 63;
            As[kk*64 + ll] = g_ycm[((size_t)(b*HH + k0 + kk))*LL + l0 + ll];
        }
        #pragma unroll
        for (int t = 0; t < 4; t++) {
            int idx = tid + t*256;
            int gg = idx >> 4, kk = idx & 15;
            Bs1[kk*68 + gg] = W[(g0 + gg)*HH + k0 + kk];
            Bs2[kk*68 + gg] = W[(g0 + 256 + gg)*HH + k0 + kk];
        }
        __syncthreads();
        #pragma unroll
        for (int kk = 0; kk < 16; kk++) {
            float4 a  = *(const float4*)&As [kk*64 + ty*4];
            float4 b1 = *(const float4*)&Bs1[kk*68 + tx*4];
            float4 b2 = *(const float4*)&Bs2[kk*68 + tx*4];
            float av[4]  = {a.x, a.y, a.z, a.w};
            float b1v[4] = {b1.x, b1.y, b1.z, b1.w};
            float b2v[4] = {b2.x, b2.y, b2.z, b2.w};
            #pragma unroll
            for (int r = 0; r < 4; r++)
                #pragma unroll
                for (int c = 0; c < 4; c++) {
                    acc1[r][c] = fmaf(av[r], b1v[c], acc1[r][c]);
                    acc2[r][c] = fmaf(av[r], b2v[c], acc2[r][c]);
                }
        }
        __syncthreads();
    }
    #pragma unroll
    for (int r = 0; r < 4; r++) {
        size_t orow = ((size_t)(b*LL + l0 + ty*4 + r))*HH + g0 + tx*4;
        #pragma unroll
        for (int c = 0; c < 4; c++) {
            float z1 = acc1[r][c] + bias[g0 + tx*4 + c];
            float z2 = acc2[r][c] + bias[256 + g0 + tx*4 + c];
            float sig = 1.0f/(1.0f + expf(-z2));
            g_hT[orow + c] += z1*sig;
        }
    }
}

// ---------------------------------------------------------------------------
// Decoder: (B*L,256) @ (256,512) + b -> out
// ---------------------------------------------------------------------------
__global__ void dec_kernel(const float* __restrict__ W,
                           const float* __restrict__ bias,
                           float* __restrict__ out) {
    __shared__ float As[16*68];
    __shared__ float Bs[16*64];
    int tid = threadIdx.x;
    int r0 = blockIdx.x * 64;
    int m0 = blockIdx.y * 64;
    int tx = tid & 15, ty = tid >> 4;
    float acc[4][4] = {{0}};
    for (int k0 = 0; k0 < HH; k0 += 16) {
        #pragma unroll
        for (int t = 0; t < 4; t++) {
            int idx = tid + t*256;
            int row = idx >> 4, col = idx & 15;
            As[col*68 + row] = g_hT[((size_t)(m0 + row))*HH + k0 + col];
        }
        #pragma unroll
        for (int t = 0; t < 4; t++) {
            int idx = tid + t*256;
            int kk = idx >> 6, rr = idx & 63;
            Bs[kk*64 + rr] = W[(k0 + kk)*REPR + r0 + rr];
        }
        __syncthreads();
        #pragma unroll
        for (int kk = 0; kk < 16; kk++) {
            float4 a = *(const float4*)&As[kk*68 + ty*4];
            float4 bb = *(const float4*)&Bs[kk*64 + tx*4];
            float av[4] = {a.x, a.y, a.z, a.w};
            float bv[4] = {bb.x, bb.y, bb.z, bb.w};
            #pragma unroll
            for (int r = 0; r < 4; r++)
                #pragma unroll
                for (int c = 0; c < 4; c++)
                    acc[r][c] = fmaf(av[r], bv[c], acc[r][c]);
        }
        __syncthreads();
    }
    #pragma unroll
    for (int r = 0; r < 4; r++) {
        size_t orow = ((size_t)(m0 + ty*4 + r))*REPR + r0 + tx*4;
        #pragma unroll
        for (int c = 0; c < 4; c++)
            out[orow + c] = acc[r][c] + bias[r0 + tx*4 + c];
    }
}

// ---------------------------------------------------------------------------
extern "C" void kernel_launch(void* const* d_in, const int* in_sizes, int n_in,
                              void* d_out, int out_size) {
    const float* x        = (const float*)d_in[0];
    const float* embed_W  = (const float*)d_in[1];
    const float* embed_b  = (const float*)d_in[2];
    const float* log_dt   = (const float*)d_in[3];
    const float* A_log_re = (const float*)d_in[4];
    const float* A_im     = (const float*)d_in[5];
    const float* C_re     = (const float*)d_in[6];
    const float* C_im     = (const float*)d_in[7];
    const float* D_skip   = (const float*)d_in[8];
    const float* out_W    = (const float*)d_in[9];
    const float* out_b    = (const float*)d_in[10];
    const float* ln_g     = (const float*)d_in[11];
    const float* ln_b     = (const float*)d_in[12];
    const float* dec_W    = (const float*)d_in[13];
    const float* dec_b    = (const float*)d_in[14];
    float* out = (float*)d_out;

    static int smem_set = 0;
    if (!smem_set) {
        cudaFuncSetAttribute(embed_kernel, cudaFuncAttributeMaxDynamicSharedMemorySize,
                             FIN*HH*sizeof(float));
        smem_set = 1;
    }

    precompute_kernel<<<(NLAYER*HH*NS + 255)/256, 256>>>(log_dt, A_log_re, A_im, C_re, C_im);
    embed_kernel<<<BB*LL/32, 256, FIN*HH*sizeof(float)>>>(x, embed_W, embed_b);
    for (int i = 0; i < NLAYER; i++) {
        ln_kernel<<<BB*LL/32, 256>>>(ln_g + i*HH, ln_b + i*HH);
        scan_kernel<<<512, 64>>>(i, D_skip + i*HH);
        glu_kernel<<<dim3(4, BB*LL/64), 256>>>(out_W + (size_t)i*G2*HH, out_b + i*G2);
    }
    dec_kernel<<<dim3(REPR/64, BB*LL/64), 256>>>(dec_W, dec_b, out);
}

// round 3
// speedup vs baseline: 1.7826x; 1.5493x over previous
#include <cuda_runtime.h>
#include <math.h>

#define BB 16
#define LL 2048
#define HH 256
#define NS 64
#define NLAYER 4
#define FIN 75
#define G2 512
#define REPR 512

// ---- device scratch ----
__device__ float g_hT[BB*LL*HH];     // residual stream, token-major (B,L,H)
__device__ float g_ucm[BB*HH*LL];    // LN output, channel-major (B,H,L)
__device__ float g_ycm[BB*HH*LL];    // scan output, channel-major
__device__ float g_wr[NLAYER*HH*NS];
__device__ float g_wi[NLAYER*HH*NS];
__device__ float g_cr[NLAYER*HH*NS];
__device__ float g_ci[NLAYER*HH*NS];

__device__ __forceinline__ unsigned cvt_tf32(float f) {
    unsigned r;
    asm("cvt.rna.tf32.f32 %0, %1;" : "=r"(r) : "f"(f));
    return r;
}

__device__ __forceinline__ void mma_tf32(float c[4], const unsigned a[4], unsigned b0, unsigned b1) {
    asm volatile("mma.sync.aligned.m16n8k8.row.col.f32.tf32.tf32.f32 "
                 "{%0,%1,%2,%3}, {%4,%5,%6,%7}, {%8,%9}, {%0,%1,%2,%3};"
                 : "+f"(c[0]), "+f"(c[1]), "+f"(c[2]), "+f"(c[3])
                 : "r"(a[0]), "r"(a[1]), "r"(a[2]), "r"(a[3]), "r"(b0), "r"(b1));
}

// ---------------------------------------------------------------------------
__global__ void precompute_kernel(const float* __restrict__ log_dt,
                                  const float* __restrict__ A_log_re,
                                  const float* __restrict__ A_im,
                                  const float* __restrict__ C_re,
                                  const float* __restrict__ C_im) {
    int idx = blockIdx.x * blockDim.x + threadIdx.x;
    if (idx >= NLAYER*HH*NS) return;
    int i = idx / (HH*NS);
    int h = (idx / NS) % HH;
    float dt  = expf(log_dt[i*HH + h]);
    float Are = -expf(A_log_re[idx]);
    float Aim = A_im[idx];
    float er = dt*Are, ei = dt*Aim;
    float mag = expf(er);
    float wr = mag*cosf(ei), wi = mag*sinf(ei);
    float nr = wr - 1.0f, ni = wi;
    float den = Are*Are + Aim*Aim;
    float inv = 1.0f/den;
    float qr = (nr*Are + ni*Aim)*inv;
    float qi = (ni*Are - nr*Aim)*inv;
    float cr = C_re[idx], ci = C_im[idx];
    g_wr[idx] = wr; g_wi[idx] = wi;
    g_cr[idx] = 2.0f*(cr*qr - ci*qi);
    g_ci[idx] = 2.0f*(cr*qi + ci*qr);
}

// ---------------------------------------------------------------------------
// Embed: (B*L,75) @ (75,256) + b -> g_hT token-major. W staged in smem.
// ---------------------------------------------------------------------------
__global__ void embed_kernel(const float* __restrict__ x,
                             const float* __restrict__ W,
                             const float* __restrict__ bias) {
    extern __shared__ float Ws[];
    __shared__ float xs[32*FIN];
    int t = threadIdx.x;
    for (int i = t; i < FIN*HH; i += 256) Ws[i] = W[i];
    int row0 = blockIdx.x * 32;
    for (int i = t; i < 32*FIN; i += 256) xs[i] = x[(size_t)row0*FIN + i];
    __syncthreads();
    float acc[32];
    float b = bias[t];
    #pragma unroll
    for (int r = 0; r < 32; r++) acc[r] = b;
    for (int f = 0; f < FIN; f++) {
        float wf = Ws[f*HH + t];
        #pragma unroll
        for (int r = 0; r < 32; r++) acc[r] = fmaf(xs[r*FIN + f], wf, acc[r]);
    }
    #pragma unroll
    for (int r = 0; r < 32; r++)
        g_hT[((size_t)(row0 + r))*HH + t] = acc[r];
}

// ---------------------------------------------------------------------------
// LayerNorm over H + transpose to channel-major
// ---------------------------------------------------------------------------
__global__ void ln_kernel(const float* __restrict__ gvec,
                          const float* __restrict__ bvec) {
    __shared__ float s[32][HH+1];
    __shared__ float sg[HH], sb[HH];
    int tid = threadIdx.x;
    sg[tid] = gvec[tid]; sb[tid] = bvec[tid];
    int blk = blockIdx.x;
    int b = blk / (LL/32);
    int l0 = (blk % (LL/32)) * 32;
    int warp = tid >> 5, lane = tid & 31;
    __syncthreads();
    for (int tt = 0; tt < 4; tt++) {
        int t = warp*4 + tt;
        const float* p = g_hT + ((size_t)(b*LL + l0 + t))*HH;
        float v[8];
        float sum = 0.f;
        #pragma unroll
        for (int j = 0; j < 8; j++) { v[j] = p[lane + 32*j]; sum += v[j]; }
        #pragma unroll
        for (int o = 16; o; o >>= 1) sum += __shfl_xor_sync(0xffffffffu, sum, o);
        float mean = sum * (1.0f/HH);
        float var = 0.f;
        #pragma unroll
        for (int j = 0; j < 8; j++) { float d = v[j]-mean; var = fmaf(d, d, var); }
        #pragma unroll
        for (int o = 16; o; o >>= 1) var += __shfl_xor_sync(0xffffffffu, var, o);
        float rstd = rsqrtf(var*(1.0f/HH) + 1e-5f);
        #pragma unroll
        for (int j = 0; j < 8; j++) {
            int c = lane + 32*j;
            s[t][c] = (v[j]-mean)*rstd*sg[c] + sb[c];
        }
    }
    __syncthreads();
    #pragma unroll 4
    for (int it = 0; it < 32; it++) {
        int h = it*8 + (tid >> 5);
        int ll = tid & 31;
        g_ucm[((size_t)(b*HH + h))*LL + l0 + ll] = s[ll][h];
    }
}

__device__ __forceinline__ float gelu_f(float v) {
    float x3 = v*v*v;
    return 0.5f*v*(1.0f + tanhf(fmaf(0.0356774081f, x3, 0.7978845608f*v)));
}

// ---------------------------------------------------------------------------
// Diagonal-SSM scan: 8 lanes/channel, 8 complex states/lane, 4 ch/warp.
// Per-step partials go to smem; a separate reduce loop sums them, keeping the
// only cross-step serial chain the 2-FMA state update.
// ---------------------------------------------------------------------------
__global__ void __launch_bounds__(128) scan_kernel(int layer, const float* __restrict__ Dski) {
    __shared__ float buf[4][32*33];            // per-warp [lane][t] stride 33
    int warp = threadIdx.x >> 5, lane = threadIdx.x & 31;
    int warpId = blockIdx.x*4 + warp;          // 0..1023
    int s = lane & 7;
    int chl = lane >> 3;
    int ch = warpId*4 + chl;                   // row in g_ucm
    int h = ch & (HH-1);
    int base = layer*HH*NS + h*NS + s*8;
    float wr[8], wi[8], cr[8], ci[8];
    #pragma unroll
    for (int k = 0; k < 8; k++) {
        wr[k] = g_wr[base+k]; wi[k] = g_wi[base+k];
        cr[k] = g_cr[base+k]; ci[k] = g_ci[base+k];
    }
    float sr[8], si[8];
    #pragma unroll
    for (int k = 0; k < 8; k++) { sr[k] = 0.f; si[k] = 0.f; }
    float D = Dski[h];
    const float* u = g_ucm + (size_t)ch*LL;
    float* wbuf = &buf[warp][0];
    int srcbase = lane & ~7;

    for (int l0 = 0; l0 < LL; l0 += 32) {
        float u0 = u[l0 + s];
        float u1 = u[l0 + 8 + s];
        float u2 = u[l0 + 16 + s];
        float u3 = u[l0 + 24 + s];
        #pragma unroll
        for (int t = 0; t < 32; t++) {
            float ut = (t < 8) ? u0 : (t < 16) ? u1 : (t < 24) ? u2 : u3;
            float uk = __shfl_sync(0xffffffffu, ut, srcbase + (t & 7));
            #pragma unroll
            for (int k = 0; k < 8; k++) {
                float tr = fmaf(wr[k], sr[k], fmaf(-wi[k], si[k], uk));
                float ti = fmaf(wr[k], si[k], wi[k]*sr[k]);
                sr[k] = tr; si[k] = ti;
            }
            float a0 = fmaf(cr[0], sr[0], -ci[0]*si[0]);
            float a1 = fmaf(cr[1], sr[1], -ci[1]*si[1]);
            float a2 = fmaf(cr[2], sr[2], -ci[2]*si[2]);
            float a3 = fmaf(cr[3], sr[3], -ci[3]*si[3]);
            a0 = fmaf(cr[4], sr[4], a0); a0 = fmaf(-ci[4], si[4], a0);
            a1 = fmaf(cr[5], sr[5], a1); a1 = fmaf(-ci[5], si[5], a1);
            a2 = fmaf(cr[6], sr[6], a2); a2 = fmaf(-ci[6], si[6], a2);
            a3 = fmaf(cr[7], sr[7], a3); a3 = fmaf(-ci[7], si[7], a3);
            float c = (a0 + a1) + (a2 + a3);
            if ((t & 7) == s) c = fmaf(D, uk, c);   // exactly one lane per group adds skip
            wbuf[lane*33 + t] = c;
        }
        __syncwarp();
        float* y = g_ycm + (size_t)ch*LL + l0;
        #pragma unroll
        for (int i = 0; i < 4; i++) {
            int t = (lane & 7) + 8*i;
            float sum = 0.f;
            #pragma unroll
            for (int q = 0; q < 8; q++)
                sum += wbuf[(chl*8 + q)*33 + t];
            y[t] = gelu_f(sum);
        }
        __syncwarp();
    }
}

// ---------------------------------------------------------------------------
// GLU out-projection + residual, tf32 tensor cores.
// Block tile: 128(l) x 64(g) for BOTH z1 (g) and z2 (g+256). K=256 in 32-chunks.
// 8 warps = 4(m) x 2(n), warp tile 32x32 per matrix.
// ---------------------------------------------------------------------------
__global__ void __launch_bounds__(256) glu_tc_kernel(const float* __restrict__ W,
                                                     const float* __restrict__ bias) {
    __shared__ float As[32*136];     // [k][l], stride 136 (136%32==8 -> conflict-free frags)
    __shared__ float Bs1[64*36];     // [g][k], stride 36 (4g+k distinct)
    __shared__ float Bs2[64*36];
    int tid = threadIdx.x;
    int warp = tid >> 5, lane = tid & 31;
    int wm = warp & 3, wn = warp >> 2;
    int gid = lane >> 2, tig = lane & 3;
    int g0 = blockIdx.x * 64;
    int mt = blockIdx.y;
    int b  = mt >> 4;
    int l0 = (mt & 15) * 128;

    float acc1[2][4][4], acc2[2][4][4];
    #pragma unroll
    for (int i = 0; i < 2; i++)
        #pragma unroll
        for (int j = 0; j < 4; j++)
            #pragma unroll
            for (int q = 0; q < 4; q++) { acc1[i][j][q] = 0.f; acc2[i][j][q] = 0.f; }

    for (int k0 = 0; k0 < HH; k0 += 32) {
        // A: 32 k-rows x 128 l floats (gmem l-contiguous)
        #pragma unroll
        for (int i = 0; i < 4; i++) {
            int f4 = tid + i*256;
            int kk = f4 >> 5, lq = f4 & 31;
            float4 v = *(const float4*)&g_ycm[((size_t)(b*HH + k0 + kk))*LL + l0 + lq*4];
            unsigned* dst = (unsigned*)&As[kk*136 + lq*4];
            dst[0] = cvt_tf32(v.x); dst[1] = cvt_tf32(v.y);
            dst[2] = cvt_tf32(v.z); dst[3] = cvt_tf32(v.w);
        }
        // B: 64 g-rows x 32 k floats each matrix (gmem k-contiguous)
        #pragma unroll
        for (int i = 0; i < 2; i++) {
            int f4 = tid + i*256;
            int gg = f4 >> 3, kq = f4 & 7;
            float4 v1 = *(const float4*)&W[(size_t)(g0 + gg)*HH + k0 + kq*4];
            float4 v2 = *(const float4*)&W[(size_t)(g0 + 256 + gg)*HH + k0 + kq*4];
            unsigned* d1 = (unsigned*)&Bs1[gg*36 + kq*4];
            unsigned* d2 = (unsigned*)&Bs2[gg*36 + kq*4];
            d1[0] = cvt_tf32(v1.x); d1[1] = cvt_tf32(v1.y);
            d1[2] = cvt_tf32(v1.z); d1[3] = cvt_tf32(v1.w);
            d2[0] = cvt_tf32(v2.x); d2[1] = cvt_tf32(v2.y);
            d2[2] = cvt_tf32(v2.z); d2[3] = cvt_tf32(v2.w);
        }
        __syncthreads();
        #pragma unroll
        for (int k8 = 0; k8 < 32; k8 += 8) {
            unsigned a[2][4];
            #pragma unroll
            for (int m2 = 0; m2 < 2; m2++) {
                int l = wm*32 + m2*16 + gid;
                a[m2][0] = __float_as_uint(As[(k8 + tig)*136 + l]);
                a[m2][1] = __float_as_uint(As[(k8 + tig)*136 + l + 8]);
                a[m2][2] = __float_as_uint(As[(k8 + 4 + tig)*136 + l]);
                a[m2][3] = __float_as_uint(As[(k8 + 4 + tig)*136 + l + 8]);
            }
            #pragma unroll
            for (int nt = 0; nt < 4; nt++) {
                int n = wn*32 + nt*8 + gid;
                unsigned b10 = __float_as_uint(Bs1[n*36 + k8 + tig]);
                unsigned b11 = __float_as_uint(Bs1[n*36 + k8 + 4 + tig]);
                unsigned b20 = __float_as_uint(Bs2[n*36 + k8 + tig]);
                unsigned b21 = __float_as_uint(Bs2[n*36 + k8 + 4 + tig]);
                #pragma unroll
                for (int m2 = 0; m2 < 2; m2++) {
                    mma_tf32(acc1[m2][nt], a[m2], b10, b11);
                    mma_tf32(acc2[m2][nt], a[m2], b20, b21);
                }
            }
        }
        __syncthreads();
    }
    // epilogue: z1*sigmoid(z2), residual add
    #pragma unroll
    for (int m2 = 0; m2 < 2; m2++) {
        #pragma unroll
        for (int nt = 0; nt < 4; nt++) {
            #pragma unroll
            for (int q = 0; q < 4; q++) {
                int row = l0 + wm*32 + m2*16 + gid + ((q >> 1) ? 8 : 0);
                int col = g0 + wn*32 + nt*8 + 2*tig + (q & 1);
                float z1 = acc1[m2][nt][q] + bias[col];
                float z2 = acc2[m2][nt][q] + bias[col + 256];
                float sig = 1.0f/(1.0f + expf(-z2));
                g_hT[((size_t)(b*LL + row))*HH + col] += z1*sig;
            }
        }
    }
}

// ---------------------------------------------------------------------------
// Decoder tf32: (B*L,256) @ (256,512) + b -> out. Block 128(m) x 64(r).
// ---------------------------------------------------------------------------
__global__ void __launch_bounds__(256) dec_tc_kernel(const float* __restrict__ W,
                                                     const float* __restrict__ bias,
                                                     float* __restrict__ out) {
    __shared__ float As[128*36];     // [l][k], stride 36
    __shared__ float Bs[32*72];      // [k][r], stride 72 (8k+r distinct)
    int tid = threadIdx.x;
    int warp = tid >> 5, lane = tid & 31;
    int wm = warp & 3, wn = warp >> 2;
    int gid = lane >> 2, tig = lane & 3;
    int r0 = blockIdx.x * 64;
    int m0 = blockIdx.y * 128;

    float acc[2][4][4];
    #pragma unroll
    for (int i = 0; i < 2; i++)
        #pragma unroll
        for (int j = 0; j < 4; j++)
            #pragma unroll
            for (int q = 0; q < 4; q++) acc[i][j][q] = 0.f;

    for (int k0 = 0; k0 < HH; k0 += 32) {
        #pragma unroll
        for (int i = 0; i < 4; i++) {
            int f4 = tid + i*256;
            int l = f4 >> 3, kq = f4 & 7;
            float4 v = *(const float4*)&g_hT[((size_t)(m0 + l))*HH + k0 + kq*4];
            unsigned* dst = (unsigned*)&As[l*36 + kq*4];
            dst[0] = cvt_tf32(v.x); dst[1] = cvt_tf32(v.y);
            dst[2] = cvt_tf32(v.z); dst[3] = cvt_tf32(v.w);
        }
        #pragma unroll
        for (int i = 0; i < 2; i++) {
            int f4 = tid + i*256;
            int kk = f4 >> 4, rq = f4 & 15;
            float4 v = *(const float4*)&W[(size_t)(k0 + kk)*REPR + r0 + rq*4];
            unsigned* dst = (unsigned*)&Bs[kk*72 + rq*4];
            dst[0] = cvt_tf32(v.x); dst[1] = cvt_tf32(v.y);
            dst[2] = cvt_tf32(v.z); dst[3] = cvt_tf32(v.w);
        }
        __syncthreads();
        #pragma unroll
        for (int k8 = 0; k8 < 32; k8 += 8) {
            unsigned a[2][4];
            #pragma unroll
            for (int m2 = 0; m2 < 2; m2++) {
                int l = wm*32 + m2*16 + gid;
                a[m2][0] = __float_as_uint(As[l*36 + k8 + tig]);
                a[m2][1] = __float_as_uint(As[(l + 8)*36 + k8 + tig]);
                a[m2][2] = __float_as_uint(As[l*36 + k8 + 4 + tig]);
                a[m2][3] = __float_as_uint(As[(l + 8)*36 + k8 + 4 + tig]);
            }
            #pragma unroll
            for (int nt = 0; nt < 4; nt++) {
                int n = wn*32 + nt*8 + gid;
                unsigned b0 = __float_as_uint(Bs[(k8 + tig)*72 + n]);
                unsigned b1 = __float_as_uint(Bs[(k8 + 4 + tig)*72 + n]);
                #pragma unroll
                for (int m2 = 0; m2 < 2; m2++)
                    mma_tf32(acc[m2][nt], a[m2], b0, b1);
            }
        }
        __syncthreads();
    }
    #pragma unroll
    for (int m2 = 0; m2 < 2; m2++) {
        #pragma unroll
        for (int nt = 0; nt < 4; nt++) {
            #pragma unroll
            for (int q = 0; q < 4; q++) {
                int row = m0 + wm*32 + m2*16 + gid + ((q >> 1) ? 8 : 0);
                int col = r0 + wn*32 + nt*8 + 2*tig + (q & 1);
                out[(size_t)row*REPR + col] = acc[m2][nt][q] + bias[col];
            }
        }
    }
}

// ---------------------------------------------------------------------------
extern "C" void kernel_launch(void* const* d_in, const int* in_sizes, int n_in,
                              void* d_out, int out_size) {
    const float* x        = (const float*)d_in[0];
    const float* embed_W  = (const float*)d_in[1];
    const float* embed_b  = (const float*)d_in[2];
    const float* log_dt   = (const float*)d_in[3];
    const float* A_log_re = (const float*)d_in[4];
    const float* A_im     = (const float*)d_in[5];
    const float* C_re     = (const float*)d_in[6];
    const float* C_im     = (const float*)d_in[7];
    const float* D_skip   = (const float*)d_in[8];
    const float* out_W    = (const float*)d_in[9];
    const float* out_b    = (const float*)d_in[10];
    const float* ln_g     = (const float*)d_in[11];
    const float* ln_b     = (const float*)d_in[12];
    const float* dec_W    = (const float*)d_in[13];
    const float* dec_b    = (const float*)d_in[14];
    float* out = (float*)d_out;

    static int smem_set = 0;
    if (!smem_set) {
        cudaFuncSetAttribute(embed_kernel, cudaFuncAttributeMaxDynamicSharedMemorySize,
                             FIN*HH*sizeof(float));
        smem_set = 1;
    }

    precompute_kernel<<<(NLAYER*HH*NS + 255)/256, 256>>>(log_dt, A_log_re, A_im, C_re, C_im);
    embed_kernel<<<BB*LL/32, 256, FIN*HH*sizeof(float)>>>(x, embed_W, embed_b);
    for (int i = 0; i < NLAYER; i++) {
        ln_kernel<<<BB*LL/32, 256>>>(ln_g + i*HH, ln_b + i*HH);
        scan_kernel<<<256, 128>>>(i, D_skip + i*HH);
        glu_tc_kernel<<<dim3(4, BB*LL/128), 256>>>(out_W + (size_t)i*G2*HH, out_b + i*G2);
    }
    dec_tc_kernel<<<dim3(REPR/64, BB*LL/128), 256>>>(dec_W, dec_b, out);
}

// round 4
// speedup vs baseline: 2.2407x; 1.2570x over previous
#include <cuda_runtime.h>
#include <math.h>

#define BB 16
#define LL 2048
#define HH 256
#define NS 64
#define NLAYER 4
#define FIN 75
#define G2 512
#define REPR 512
#define TCH 128      // chunk length
#define NCHUNK 16    // LL/TCH
#define JCOLS 256    // NCHUNK*BB

// ---- device scratch ----
__device__ float g_hT[BB*LL*HH];     // residual stream, token-major (B,L,H)
__device__ float g_ucm[BB*HH*LL];    // LN output, channel-major (B,H,L)
__device__ float g_ycm[BB*HH*LL];    // scan output, channel-major
__device__ float g_wr[NLAYER*HH*NS];
__device__ float g_wi[NLAYER*HH*NS];
__device__ float g_cr[NLAYER*HH*NS];
__device__ float g_ci[NLAYER*HH*NS];
// scan-as-GEMM structures
__device__ float g_P[(size_t)NLAYER*HH*TCH*128];      // [l,h][tau][n2]  (Re|Im of w^{127-tau})
__device__ float g_AC[(size_t)NLAYER*HH*256*TCH];     // [l,h][k=256][t] (KmatT rows 0..127, QT rows 128..255)
__device__ float g_F[(size_t)HH*JCOLS*128];           // [h][j][n2]
__device__ float g_S[(size_t)HH*JCOLS*128];           // [h][j][n2]
__device__ float g_wTr[NLAYER*HH*NS];
__device__ float g_wTi[NLAYER*HH*NS];

__device__ __forceinline__ unsigned cvt_tf32(float f) {
    unsigned r;
    asm("cvt.rna.tf32.f32 %0, %1;" : "=r"(r) : "f"(f));
    return r;
}

__device__ __forceinline__ void mma_tf32(float c[4], const unsigned a[4], unsigned b0, unsigned b1) {
    asm volatile("mma.sync.aligned.m16n8k8.row.col.f32.tf32.tf32.f32 "
                 "{%0,%1,%2,%3}, {%4,%5,%6,%7}, {%8,%9}, {%0,%1,%2,%3};"
                 : "+f"(c[0]), "+f"(c[1]), "+f"(c[2]), "+f"(c[3])
                 : "r"(a[0]), "r"(a[1]), "r"(a[2]), "r"(a[3]), "r"(b0), "r"(b1));
}

__device__ __forceinline__ float gelu_f(float v) {
    float x3 = v*v*v;
    return 0.5f*v*(1.0f + tanhf(fmaf(0.0356774081f, x3, 0.7978845608f*v)));
}

// ---------------------------------------------------------------------------
__global__ void precompute_kernel(const float* __restrict__ log_dt,
                                  const float* __restrict__ A_log_re,
                                  const float* __restrict__ A_im,
                                  const float* __restrict__ C_re,
                                  const float* __restrict__ C_im) {
    int idx = blockIdx.x * blockDim.x + threadIdx.x;
    if (idx >= NLAYER*HH*NS) return;
    int i = idx / (HH*NS);
    int h = (idx / NS) % HH;
    float dt  = expf(log_dt[i*HH + h]);
    float Are = -expf(A_log_re[idx]);
    float Aim = A_im[idx];
    float er = dt*Are, ei = dt*Aim;
    float mag = expf(er);
    float wr = mag*cosf(ei), wi = mag*sinf(ei);
    float nr = wr - 1.0f, ni = wi;
    float den = Are*Are + Aim*Aim;
    float inv = 1.0f/den;
    float qr = (nr*Are + ni*Aim)*inv;
    float qi = (ni*Are - nr*Aim)*inv;
    float cr = C_re[idx], ci = C_im[idx];
    g_wr[idx] = wr; g_wi[idx] = wi;
    g_cr[idx] = 2.0f*(cr*qr - ci*qi);
    g_ci[idx] = 2.0f*(cr*qi + ci*qr);
}

// ---------------------------------------------------------------------------
// Precompute P, AC (= [KmatT; QT]), w^T per (layer, h).
// Powers w^d (d=0..128) built once in smem, all global writes coalesced.
// ---------------------------------------------------------------------------
__global__ void precompute2_kernel() {
    extern __shared__ float ps[];              // wpr[129][68] | wpi[129][68] | sK[128]
    float* wpr = ps;
    float* wpi = ps + 129*68;
    float* sK  = wpi + 129*68;
    int tid = threadIdx.x;                     // 128 threads
    int lh = blockIdx.x;                       // layer*HH + h
    int ib = lh*NS;
    if (tid < 64) {
        int n = tid;
        float wr = g_wr[ib+n], wi = g_wi[ib+n];
        float pr = 1.f, pi = 0.f;
        for (int d = 0; d <= 128; d++) {
            wpr[d*68+n] = pr; wpi[d*68+n] = pi;
            float nr = pr*wr - pi*wi;
            float ni = pr*wi + pi*wr;
            pr = nr; pi = ni;
        }
    }
    __syncthreads();
    {   // K[d] = Re(sum_n Cd_n w^d)
        int d = tid;
        float s = 0.f;
        for (int n = 0; n < 64; n++)
            s += g_cr[ib+n]*wpr[d*68+n] - g_ci[ib+n]*wpi[d*68+n];
        sK[d] = s;
    }
    if (tid < 64) {
        g_wTr[ib+tid] = wpr[128*68+tid];
        g_wTi[ib+tid] = wpi[128*68+tid];
    }
    __syncthreads();
    // P[tau][n2]: Re|Im of w^{127-tau}
    size_t pbase = (size_t)lh*TCH*128;
    int n2 = tid;
    for (int tau = 0; tau < TCH; tau++) {
        float v = (n2 < 64) ? wpr[(127-tau)*68 + n2] : wpi[(127-tau)*68 + (n2-64)];
        g_P[pbase + (size_t)tau*128 + n2] = v;
    }
    // AC rows 0..127: KmatT[tau][t] = K[t-tau] for t>=tau
    size_t acbase = (size_t)lh*256*TCH;
    int t = tid;
    for (int tau = 0; tau < TCH; tau++)
        g_AC[acbase + (size_t)tau*TCH + t] = (t >= tau) ? sK[t - tau] : 0.f;
    // AC rows 128..255: QT[n2][t] = Re(Cd w^{t+1}) | -Im(Cd w^{t+1})
    for (int q2 = 0; q2 < 128; q2++) {
        int n = q2 & 63;
        float cr = g_cr[ib+n], ci = g_ci[ib+n];
        float wr = wpr[(t+1)*68 + n], wi = wpi[(t+1)*68 + n];
        float v = (q2 < 64) ? (cr*wr - ci*wi) : -(cr*wi + ci*wr);
        g_AC[acbase + (size_t)(128 + q2)*TCH + t] = v;
    }
}

// ---------------------------------------------------------------------------
// Embed: (B*L,75) @ (75,256) + b -> g_hT token-major. W staged in smem.
// ---------------------------------------------------------------------------
__global__ void embed_kernel(const float* __restrict__ x,
                             const float* __restrict__ W,
                             const float* __restrict__ bias) {
    extern __shared__ float Ws[];
    __shared__ float xs[32*FIN];
    int t = threadIdx.x;
    for (int i = t; i < FIN*HH; i += 256) Ws[i] = W[i];
    int row0 = blockIdx.x * 32;
    for (int i = t; i < 32*FIN; i += 256) xs[i] = x[(size_t)row0*FIN + i];
    __syncthreads();
    float acc[32];
    float b = bias[t];
    #pragma unroll
    for (int r = 0; r < 32; r++) acc[r] = b;
    for (int f = 0; f < FIN; f++) {
        float wf = Ws[f*HH + t];
        #pragma unroll
        for (int r = 0; r < 32; r++) acc[r] = fmaf(xs[r*FIN + f], wf, acc[r]);
    }
    #pragma unroll
    for (int r = 0; r < 32; r++)
        g_hT[((size_t)(row0 + r))*HH + t] = acc[r];
}

// ---------------------------------------------------------------------------
// LayerNorm over H + transpose to channel-major
// ---------------------------------------------------------------------------
__global__ void ln_kernel(const float* __restrict__ gvec,
                          const float* __restrict__ bvec) {
    __shared__ float s[32][HH+1];
    __shared__ float sg[HH], sb[HH];
    int tid = threadIdx.x;
    sg[tid] = gvec[tid]; sb[tid] = bvec[tid];
    int blk = blockIdx.x;
    int b = blk / (LL/32);
    int l0 = (blk % (LL/32)) * 32;
    int warp = tid >> 5, lane = tid & 31;
    __syncthreads();
    for (int tt = 0; tt < 4; tt++) {
        int t = warp*4 + tt;
        const float* p = g_hT + ((size_t)(b*LL + l0 + t))*HH;
        float v[8];
        float sum = 0.f;
        #pragma unroll
        for (int j = 0; j < 8; j++) { v[j] = p[lane + 32*j]; sum += v[j]; }
        #pragma unroll
        for (int o = 16; o; o >>= 1) sum += __shfl_xor_sync(0xffffffffu, sum, o);
        float mean = sum * (1.0f/HH);
        float var = 0.f;
        #pragma unroll
        for (int j = 0; j < 8; j++) { float d = v[j]-mean; var = fmaf(d, d, var); }
        #pragma unroll
        for (int o = 16; o; o >>= 1) var += __shfl_xor_sync(0xffffffffu, var, o);
        float rstd = rsqrtf(var*(1.0f/HH) + 1e-5f);
        #pragma unroll
        for (int j = 0; j < 8; j++) {
            int c = lane + 32*j;
            s[t][c] = (v[j]-mean)*rstd*sg[c] + sb[c];
        }
    }
    __syncthreads();
    #pragma unroll 4
    for (int it = 0; it < 32; it++) {
        int h = it*8 + (tid >> 5);
        int ll = tid & 31;
        g_ucm[((size_t)(b*HH + h))*LL + l0 + ll] = s[ll][h];
    }
}

// ---------------------------------------------------------------------------
// GEMM-F: per h, F[j,n2] = sum_tau U[j,tau] * P[tau,n2]   (M=256j, N=128, K=128)
// Block: 128(m) x 128(n), 512 threads (16 warps, 4m x 4n, warp 32x32).
// ---------------------------------------------------------------------------
__global__ void __launch_bounds__(512) gemm_f_kernel(int layer) {
    __shared__ float As[128*36];
    __shared__ float Bs[32*136];
    int tid = threadIdx.x;
    int warp = tid >> 5, lane = tid & 31;
    int wm = warp & 3, wn = warp >> 2;
    int gid = lane >> 2, tig = lane & 3;
    int h = blockIdx.y;
    int j0 = blockIdx.x * 128;
    const float* P = g_P + (size_t)(layer*HH + h)*TCH*128;

    float acc[2][4][4];
    #pragma unroll
    for (int i = 0; i < 2; i++)
        #pragma unroll
        for (int j = 0; j < 4; j++)
            #pragma unroll
            for (int q = 0; q < 4; q++) acc[i][j][q] = 0.f;

    for (int k0 = 0; k0 < TCH; k0 += 32) {
        #pragma unroll
        for (int i = 0; i < 2; i++) {
            int f4 = tid + i*512;
            int row = f4 >> 3, kq = f4 & 7;
            int j = j0 + row;
            int c = j >> 4, bb = j & 15;
            float4 v = *(const float4*)&g_ucm[((size_t)(bb*HH + h))*LL + c*TCH + k0 + kq*4];
            unsigned* dst = (unsigned*)&As[row*36 + kq*4];
            dst[0] = cvt_tf32(v.x); dst[1] = cvt_tf32(v.y);
            dst[2] = cvt_tf32(v.z); dst[3] = cvt_tf32(v.w);
        }
        #pragma unroll
        for (int i = 0; i < 2; i++) {
            int f4 = tid + i*512;
            int k = f4 >> 5, tq = f4 & 31;
            float4 v = *(const float4*)&P[(size_t)(k0 + k)*128 + tq*4];
            unsigned* dst = (unsigned*)&Bs[k*136 + tq*4];
            dst[0] = cvt_tf32(v.x); dst[1] = cvt_tf32(v.y);
            dst[2] = cvt_tf32(v.z); dst[3] = cvt_tf32(v.w);
        }
        __syncthreads();
        #pragma unroll
        for (int k8 = 0; k8 < 32; k8 += 8) {
            unsigned a[2][4];
            #pragma unroll
            for (int m2 = 0; m2 < 2; m2++) {
                int l = wm*32 + m2*16 + gid;
                a[m2][0] = __float_as_uint(As[l*36 + k8 + tig]);
                a[m2][1] = __float_as_uint(As[(l + 8)*36 + k8 + tig]);
                a[m2][2] = __float_as_uint(As[l*36 + k8 + 4 + tig]);
                a[m2][3] = __float_as_uint(As[(l + 8)*36 + k8 + 4 + tig]);
            }
            #pragma unroll
            for (int nt = 0; nt < 4; nt++) {
                int n = wn*32 + nt*8 + gid;
                unsigned b0 = __float_as_uint(Bs[(k8 + tig)*136 + n]);
                unsigned b1 = __float_as_uint(Bs[(k8 + 4 + tig)*136 + n]);
                #pragma unroll
                for (int m2 = 0; m2 < 2; m2++)
                    mma_tf32(acc[m2][nt], a[m2], b0, b1);
            }
        }
        __syncthreads();
    }
    #pragma unroll
    for (int m2 = 0; m2 < 2; m2++) {
        #pragma unroll
        for (int nt = 0; nt < 4; nt++) {
            #pragma unroll
            for (int q = 0; q < 4; q++) {
                int row = wm*32 + m2*16 + gid + ((q >> 1) ? 8 : 0);
                int col = wn*32 + nt*8 + 2*tig + (q & 1);
                g_F[((size_t)h*JCOLS + j0 + row)*128 + col] = acc[m2][nt][q];
            }
        }
    }
}

// ---------------------------------------------------------------------------
// Chunk-scan: per (h, b, n): S_{c+1} = w^128 * S_c + F_c; store chunk-start S.
// ---------------------------------------------------------------------------
__global__ void chunkscan_kernel(int layer) {
    int g = blockIdx.x*256 + threadIdx.x;       // 256*16*64 = 262144
    int h = g >> 10;
    int r = g & 1023;
    int bb = r >> 6;
    int n = r & 63;
    int ib = (layer*HH + h)*NS + n;
    float wtr = g_wTr[ib], wti = g_wTi[ib];
    float sre = 0.f, sim = 0.f;
    size_t base = (size_t)h*JCOLS*128;
    #pragma unroll
    for (int c = 0; c < NCHUNK; c++) {
        size_t jo = base + (size_t)(c*16 + bb)*128;
        g_S[jo + n]      = sre;
        g_S[jo + 64 + n] = sim;
        float fre = g_F[jo + n];
        float fim = g_F[jo + 64 + n];
        float nr = fmaf(wtr, sre, fmaf(-wti, sim, fre));
        float ni = fmaf(wtr, sim, fmaf(wti, sre, fim));
        sre = nr; sim = ni;
    }
}

// ---------------------------------------------------------------------------
// GEMM-Y: per h, y[j,t] = [U | S][j,k] @ AC[k,t]  (M=256j, N=128t, K=256)
// Epilogue: + D*u, gelu -> g_ycm (t-contiguous coalesced stores).
// ---------------------------------------------------------------------------
__global__ void __launch_bounds__(512) gemm_y_kernel(int layer, const float* __restrict__ Dski) {
    __shared__ float As[128*36];
    __shared__ float Bs[32*136];
    int tid = threadIdx.x;
    int warp = tid >> 5, lane = tid & 31;
    int wm = warp & 3, wn = warp >> 2;
    int gid = lane >> 2, tig = lane & 3;
    int h = blockIdx.y;
    int j0 = blockIdx.x * 128;
    const float* AC = g_AC + (size_t)(layer*HH + h)*256*TCH;

    float acc[2][4][4];
    #pragma unroll
    for (int i = 0; i < 2; i++)
        #pragma unroll
        for (int j = 0; j < 4; j++)
            #pragma unroll
            for (int q = 0; q < 4; q++) acc[i][j][q] = 0.f;

    for (int k0 = 0; k0 < 256; k0 += 32) {
        #pragma unroll
        for (int i = 0; i < 2; i++) {
            int f4 = tid + i*512;
            int row = f4 >> 3, kq = f4 & 7;
            int j = j0 + row;
            float4 v;
            if (k0 < TCH) {
                int c = j >> 4, bb = j & 15;
                v = *(const float4*)&g_ucm[((size_t)(bb*HH + h))*LL + c*TCH + k0 + kq*4];
            } else {
                v = *(const float4*)&g_S[((size_t)h*JCOLS + j)*128 + (k0 - TCH) + kq*4];
            }
            unsigned* dst = (unsigned*)&As[row*36 + kq*4];
            dst[0] = cvt_tf32(v.x); dst[1] = cvt_tf32(v.y);
            dst[2] = cvt_tf32(v.z); dst[3] = cvt_tf32(v.w);
        }
        #pragma unroll
        for (int i = 0; i < 2; i++) {
            int f4 = tid + i*512;
            int k = f4 >> 5, tq = f4 & 31;
            float4 v = *(const float4*)&AC[(size_t)(k0 + k)*TCH + tq*4];
            unsigned* dst = (unsigned*)&Bs[k*136 + tq*4];
            dst[0] = cvt_tf32(v.x); dst[1] = cvt_tf32(v.y);
            dst[2] = cvt_tf32(v.z); dst[3] = cvt_tf32(v.w);
        }
        __syncthreads();
        #pragma unroll
        for (int k8 = 0; k8 < 32; k8 += 8) {
            unsigned a[2][4];
            #pragma unroll
            for (int m2 = 0; m2 < 2; m2++) {
                int l = wm*32 + m2*16 + gid;
                a[m2][0] = __float_as_uint(As[l*36 + k8 + tig]);
                a[m2][1] = __float_as_uint(As[(l + 8)*36 + k8 + tig]);
                a[m2][2] = __float_as_uint(As[l*36 + k8 + 4 + tig]);
                a[m2][3] = __float_as_uint(As[(l + 8)*36 + k8 + 4 + tig]);
            }
            #pragma unroll
            for (int nt = 0; nt < 4; nt++) {
                int n = wn*32 + nt*8 + gid;
                unsigned b0 = __float_as_uint(Bs[(k8 + tig)*136 + n]);
                unsigned b1 = __float_as_uint(Bs[(k8 + 4 + tig)*136 + n]);
                #pragma unroll
                for (int m2 = 0; m2 < 2; m2++)
                    mma_tf32(acc[m2][nt], a[m2], b0, b1);
            }
        }
        __syncthreads();
    }
    float D = Dski[h];
    #pragma unroll
    for (int m2 = 0; m2 < 2; m2++) {
        #pragma unroll
        for (int nt = 0; nt < 4; nt++) {
            #pragma unroll
            for (int q = 0; q < 4; q++) {
                int row = wm*32 + m2*16 + gid + ((q >> 1) ? 8 : 0);
                int j = j0 + row;
                int t = wn*32 + nt*8 + 2*tig + (q & 1);
                int c = j >> 4, bb = j & 15;
                size_t base = ((size_t)(bb*HH + h))*LL + c*TCH;
                float u = g_ucm[base + t];
                float yv = fmaf(D, u, acc[m2][nt][q]);
                g_ycm[base + t] = gelu_f(yv);
            }
        }
    }
}

// ---------------------------------------------------------------------------
// GLU out-projection + residual, tf32 tensor cores.
// ---------------------------------------------------------------------------
__global__ void __launch_bounds__(256) glu_tc_kernel(const float* __restrict__ W,
                                                     const float* __restrict__ bias) {
    __shared__ float As[32*136];
    __shared__ float Bs1[64*36];
    __shared__ float Bs2[64*36];
    int tid = threadIdx.x;
    int warp = tid >> 5, lane = tid & 31;
    int wm = warp & 3, wn = warp >> 2;
    int gid = lane >> 2, tig = lane & 3;
    int g0 = blockIdx.x * 64;
    int mt = blockIdx.y;
    int b  = mt >> 4;
    int l0 = (mt & 15) * 128;

    float acc1[2][4][4], acc2[2][4][4];
    #pragma unroll
    for (int i = 0; i < 2; i++)
        #pragma unroll
        for (int j = 0; j < 4; j++)
            #pragma unroll
            for (int q = 0; q < 4; q++) { acc1[i][j][q] = 0.f; acc2[i][j][q] = 0.f; }

    for (int k0 = 0; k0 < HH; k0 += 32) {
        #pragma unroll
        for (int i = 0; i < 4; i++) {
            int f4 = tid + i*256;
            int kk = f4 >> 5, lq = f4 & 31;
            float4 v = *(const float4*)&g_ycm[((size_t)(b*HH + k0 + kk))*LL + l0 + lq*4];
            unsigned* dst = (unsigned*)&As[kk*136 + lq*4];
            dst[0] = cvt_tf32(v.x); dst[1] = cvt_tf32(v.y);
            dst[2] = cvt_tf32(v.z); dst[3] = cvt_tf32(v.w);
        }
        #pragma unroll
        for (int i = 0; i < 2; i++) {
            int f4 = tid + i*256;
            int gg = f4 >> 3, kq = f4 & 7;
            float4 v1 = *(const float4*)&W[(size_t)(g0 + gg)*HH + k0 + kq*4];
            float4 v2 = *(const float4*)&W[(size_t)(g0 + 256 + gg)*HH + k0 + kq*4];
            unsigned* d1 = (unsigned*)&Bs1[gg*36 + kq*4];
            unsigned* d2 = (unsigned*)&Bs2[gg*36 + kq*4];
            d1[0] = cvt_tf32(v1.x); d1[1] = cvt_tf32(v1.y);
            d1[2] = cvt_tf32(v1.z); d1[3] = cvt_tf32(v1.w);
            d2[0] = cvt_tf32(v2.x); d2[1] = cvt_tf32(v2.y);
            d2[2] = cvt_tf32(v2.z); d2[3] = cvt_tf32(v2.w);
        }
        __syncthreads();
        #pragma unroll
        for (int k8 = 0; k8 < 32; k8 += 8) {
            unsigned a[2][4];
            #pragma unroll
            for (int m2 = 0; m2 < 2; m2++) {
                int l = wm*32 + m2*16 + gid;
                a[m2][0] = __float_as_uint(As[(k8 + tig)*136 + l]);
                a[m2][1] = __float_as_uint(As[(k8 + tig)*136 + l + 8]);
                a[m2][2] = __float_as_uint(As[(k8 + 4 + tig)*136 + l]);
                a[m2][3] = __float_as_uint(As[(k8 + 4 + tig)*136 + l + 8]);
            }
            #pragma unroll
            for (int nt = 0; nt < 4; nt++) {
                int n = wn*32 + nt*8 + gid;
                unsigned b10 = __float_as_uint(Bs1[n*36 + k8 + tig]);
                unsigned b11 = __float_as_uint(Bs1[n*36 + k8 + 4 + tig]);
                unsigned b20 = __float_as_uint(Bs2[n*36 + k8 + tig]);
                unsigned b21 = __float_as_uint(Bs2[n*36 + k8 + 4 + tig]);
                #pragma unroll
                for (int m2 = 0; m2 < 2; m2++) {
                    mma_tf32(acc1[m2][nt], a[m2], b10, b11);
                    mma_tf32(acc2[m2][nt], a[m2], b20, b21);
                }
            }
        }
        __syncthreads();
    }
    #pragma unroll
    for (int m2 = 0; m2 < 2; m2++) {
        #pragma unroll
        for (int nt = 0; nt < 4; nt++) {
            #pragma unroll
            for (int q = 0; q < 4; q++) {
                int row = l0 + wm*32 + m2*16 + gid + ((q >> 1) ? 8 : 0);
                int col = g0 + wn*32 + nt*8 + 2*tig + (q & 1);
                float z1 = acc1[m2][nt][q] + bias[col];
                float z2 = acc2[m2][nt][q] + bias[col + 256];
                float sig = 1.0f/(1.0f + expf(-z2));
                g_hT[((size_t)(b*LL + row))*HH + col] += z1*sig;
            }
        }
    }
}

// ---------------------------------------------------------------------------
// Decoder tf32: (B*L,256) @ (256,512) + b -> out. Block 128(m) x 64(r).
// ---------------------------------------------------------------------------
__global__ void __launch_bounds__(256) dec_tc_kernel(const float* __restrict__ W,
                                                     const float* __restrict__ bias,
                                                     float* __restrict__ out) {
    __shared__ float As[128*36];
    __shared__ float Bs[32*72];
    int tid = threadIdx.x;
    int warp = tid >> 5, lane = tid & 31;
    int wm = warp & 3, wn = warp >> 2;
    int gid = lane >> 2, tig = lane & 3;
    int r0 = blockIdx.x * 64;
    int m0 = blockIdx.y * 128;

    float acc[2][4][4];
    #pragma unroll
    for (int i = 0; i < 2; i++)
        #pragma unroll
        for (int j = 0; j < 4; j++)
            #pragma unroll
            for (int q = 0; q < 4; q++) acc[i][j][q] = 0.f;

    for (int k0 = 0; k0 < HH; k0 += 32) {
        #pragma unroll
        for (int i = 0; i < 4; i++) {
            int f4 = tid + i*256;
            int l = f4 >> 3, kq = f4 & 7;
            float4 v = *(const float4*)&g_hT[((size_t)(m0 + l))*HH + k0 + kq*4];
            unsigned* dst = (unsigned*)&As[l*36 + kq*4];
            dst[0] = cvt_tf32(v.x); dst[1] = cvt_tf32(v.y);
            dst[2] = cvt_tf32(v.z); dst[3] = cvt_tf32(v.w);
        }
        #pragma unroll
        for (int i = 0; i < 2; i++) {
            int f4 = tid + i*256;
            int kk = f4 >> 4, rq = f4 & 15;
            float4 v = *(const float4*)&W[(size_t)(k0 + kk)*REPR + r0 + rq*4];
            unsigned* dst = (unsigned*)&Bs[kk*72 + rq*4];
            dst[0] = cvt_tf32(v.x); dst[1] = cvt_tf32(v.y);
            dst[2] = cvt_tf32(v.z); dst[3] = cvt_tf32(v.w);
        }
        __syncthreads();
        #pragma unroll
        for (int k8 = 0; k8 < 32; k8 += 8) {
            unsigned a[2][4];
            #pragma unroll
            for (int m2 = 0; m2 < 2; m2++) {
                int l = wm*32 + m2*16 + gid;
                a[m2][0] = __float_as_uint(As[l*36 + k8 + tig]);
                a[m2][1] = __float_as_uint(As[(l + 8)*36 + k8 + tig]);
                a[m2][2] = __float_as_uint(As[l*36 + k8 + 4 + tig]);
                a[m2][3] = __float_as_uint(As[(l + 8)*36 + k8 + 4 + tig]);
            }
            #pragma unroll
            for (int nt = 0; nt < 4; nt++) {
                int n = wn*32 + nt*8 + gid;
                unsigned b0 = __float_as_uint(Bs[(k8 + tig)*72 + n]);
                unsigned b1 = __float_as_uint(Bs[(k8 + 4 + tig)*72 + n]);
                #pragma unroll
                for (int m2 = 0; m2 < 2; m2++)
                    mma_tf32(acc[m2][nt], a[m2], b0, b1);
            }
        }
        __syncthreads();
    }
    #pragma unroll
    for (int m2 = 0; m2 < 2; m2++) {
        #pragma unroll
        for (int nt = 0; nt < 4; nt++) {
            #pragma unroll
            for (int q = 0; q < 4; q++) {
                int row = m0 + wm*32 + m2*16 + gid + ((q >> 1) ? 8 : 0);
                int col = r0 + wn*32 + nt*8 + 2*tig + (q & 1);
                out[(size_t)row*REPR + col] = acc[m2][nt][q] + bias[col];
            }
        }
    }
}

// ---------------------------------------------------------------------------
extern "C" void kernel_launch(void* const* d_in, const int* in_sizes, int n_in,
                              void* d_out, int out_size) {
    const float* x        = (const float*)d_in[0];
    const float* embed_W  = (const float*)d_in[1];
    const float* embed_b  = (const float*)d_in[2];
    const float* log_dt   = (const float*)d_in[3];
    const float* A_log_re = (const float*)d_in[4];
    const float* A_im     = (const float*)d_in[5];
    const float* C_re     = (const float*)d_in[6];
    const float* C_im     = (const float*)d_in[7];
    const float* D_skip   = (const float*)d_in[8];
    const float* out_W    = (const float*)d_in[9];
    const float* out_b    = (const float*)d_in[10];
    const float* ln_g     = (const float*)d_in[11];
    const float* ln_b     = (const float*)d_in[12];
    const float* dec_W    = (const float*)d_in[13];
    const float* dec_b    = (const float*)d_in[14];
    float* out = (float*)d_out;

    const int PRE2_SMEM = (2*129*68 + 128) * sizeof(float);   // ~70.7KB
    static int smem_set = 0;
    if (!smem_set) {
        cudaFuncSetAttribute(embed_kernel, cudaFuncAttributeMaxDynamicSharedMemorySize,
                             FIN*HH*sizeof(float));
        cudaFuncSetAttribute(precompute2_kernel, cudaFuncAttributeMaxDynamicSharedMemorySize,
                             PRE2_SMEM);
        smem_set = 1;
    }

    precompute_kernel<<<(NLAYER*HH*NS + 255)/256, 256>>>(log_dt, A_log_re, A_im, C_re, C_im);
    precompute2_kernel<<<NLAYER*HH, 128, PRE2_SMEM>>>();
    embed_kernel<<<BB*LL/32, 256, FIN*HH*sizeof(float)>>>(x, embed_W, embed_b);
    for (int i = 0; i < NLAYER; i++) {
        ln_kernel<<<BB*LL/32, 256>>>(ln_g + i*HH, ln_b + i*HH);
        gemm_f_kernel<<<dim3(2, HH), 512>>>(i);
        chunkscan_kernel<<<HH*BB*NS/256, 256>>>(i);
        gemm_y_kernel<<<dim3(2, HH), 512>>>(i, D_skip + i*HH);
        glu_tc_kernel<<<dim3(4, BB*LL/128), 256>>>(out_W + (size_t)i*G2*HH, out_b + i*G2);
    }
    dec_tc_kernel<<<dim3(REPR/64, BB*LL/128), 256>>>(dec_W, dec_b, out);
}